// round 4
// baseline (speedup 1.0000x reference)
#include <cuda_runtime.h>
#include <cuda_bf16.h>
#include <cstdint>

#define NNODES   100000
#define SSAMP    16
#define NODE_DIM 128
#define EDGE_DIM 64
#define EMB_DIM  128
#define KTOT     320            // 128 self + 128 neigh-agg + 64 edge-mean

#define MT       64             // nodes per CTA tile
#define ASTRIDE  656            // bytes per A row (328 halfs; 656/4 %32 -> conflict-free ldmatrix)
#define BSTRIDE  48             // bytes per B row in a k-step buffer (16 halfs + pad)
#define BHALF    (128 * BSTRIDE)       // 6144, hi part of one buffer
#define BBUF     (2 * BHALF)           // 12288, hi+lo
#define SM_B_OFF (2 * MT * ASTRIDE)    // 83968 (after sAh, sAl)
#define SM_TOTAL (SM_B_OFF + 2 * BBUF) // 108544

// ---------------- persistent weights (device globals; no allocs) ------------
__device__ __align__(16) __nv_bfloat16 g_Wh[EMB_DIM * KTOT];  // folded W^T [n][k], hi
__device__ __align__(16) __nv_bfloat16 g_Wl[EMB_DIM * KTOT];  // lo
__device__ float g_bias[EMB_DIM];

// ---------------- helpers ----------------------------------------------------
__device__ __forceinline__ uint32_t smem_u32(const void* p) {
    uint32_t a;
    asm("{ .reg .u64 t; cvta.to.shared.u64 t, %1; cvt.u32.u64 %0, t; }" : "=r"(a) : "l"(p));
    return a;
}
__device__ __forceinline__ void ldsm_x4(uint32_t* r, uint32_t addr) {
    asm volatile("ldmatrix.sync.aligned.m8n8.x4.shared.b16 {%0,%1,%2,%3}, [%4];"
        : "=r"(r[0]), "=r"(r[1]), "=r"(r[2]), "=r"(r[3]) : "r"(addr));
}
__device__ __forceinline__ void mma16816(float* d, const uint32_t* a, const uint32_t* b) {
    asm volatile("mma.sync.aligned.m16n8k16.row.col.f32.bf16.bf16.f32 "
        "{%0,%1,%2,%3}, {%4,%5,%6,%7}, {%8,%9}, {%0,%1,%2,%3};"
        : "+f"(d[0]), "+f"(d[1]), "+f"(d[2]), "+f"(d[3])
        : "r"(a[0]), "r"(a[1]), "r"(a[2]), "r"(a[3]), "r"(b[0]), "r"(b[1]));
}
__device__ __forceinline__ void cpa16(uint32_t dst, const void* src) {
    asm volatile("cp.async.cg.shared.global [%0], [%1], 16;" :: "r"(dst), "l"(src));
}
#define CP_COMMIT() asm volatile("cp.async.commit_group;" ::: "memory")
#define CP_WAIT0()  asm volatile("cp.async.wait_group 0;" ::: "memory")

__device__ __forceinline__ void split_store(unsigned char* hrow, unsigned char* lrow,
                                            int boff, float4 v) {
    __nv_bfloat16 hx = __float2bfloat16_rn(v.x);
    __nv_bfloat16 hy = __float2bfloat16_rn(v.y);
    __nv_bfloat16 hz = __float2bfloat16_rn(v.z);
    __nv_bfloat16 hw = __float2bfloat16_rn(v.w);
    __nv_bfloat162 h01 = __halves2bfloat162(hx, hy);
    __nv_bfloat162 h23 = __halves2bfloat162(hz, hw);
    __nv_bfloat162 l01 = __floats2bfloat162_rn(v.x - __bfloat162float(hx),
                                               v.y - __bfloat162float(hy));
    __nv_bfloat162 l23 = __floats2bfloat162_rn(v.z - __bfloat162float(hz),
                                               v.w - __bfloat162float(hw));
    *(uint2*)(hrow + boff) = make_uint2(*(uint32_t*)&h01, *(uint32_t*)&h23);
    *(uint2*)(lrow + boff) = make_uint2(*(uint32_t*)&l01, *(uint32_t*)&l23);
}

// ===========================================================================
// K0: fold Wall = [W_lin ; W_edge@W_lin[128:]] -> bf16 hi/lo transposed [n][k]
// ===========================================================================
__global__ __launch_bounds__(256) void fold_weights(
        const float* __restrict__ W_edge, const float* __restrict__ b_edge,
        const float* __restrict__ W_lin,  const float* __restrict__ b_lin) {
    int kid = blockIdx.x;                  // 0..40
    if (kid == 40) {
        int j = threadIdx.x;
        if (j < EMB_DIM) {
            float acc = b_lin[j];
            for (int c = 0; c < NODE_DIM; c++)
                acc += b_edge[c] * W_lin[(NODE_DIM + c) * EMB_DIM + j];
            g_bias[j] = acc;
        }
        return;
    }
    int kk = threadIdx.x >> 7;             // 0/1
    int j  = threadIdx.x & 127;            // output col n
    #pragma unroll
    for (int r = 0; r < 4; r++) {
        int k = kid * 8 + r * 2 + kk;      // 0..319
        float w;
        if (k < 2 * NODE_DIM) {
            w = W_lin[k * EMB_DIM + j];
        } else {
            int e = k - 2 * NODE_DIM;
            float acc = 0.f;
            #pragma unroll 4
            for (int c = 0; c < NODE_DIM; c++)
                acc += W_edge[e * NODE_DIM + c] * W_lin[(NODE_DIM + c) * EMB_DIM + j];
            w = acc;
        }
        __nv_bfloat16 h = __float2bfloat16_rn(w);
        g_Wh[j * KTOT + k] = h;
        g_Wl[j * KTOT + k] = __float2bfloat16_rn(w - __bfloat162float(h));
    }
}

// ===========================================================================
// K1 (fused): per 64-node tile:
//   Phase A: warp-per-node aggregation -> split-bf16 A tile in smem [64 x 320]
//   Phase B: 20 k-steps mma.sync, B slices double-buffered via cp.async
//   Epilogue: bias + relu -> out
// ===========================================================================
__global__ __launch_bounds__(256, 2) void sage_fused(
        const float* __restrict__ node_feat,
        const float* __restrict__ edge_feat,
        const int*   __restrict__ src_idx,
        float* __restrict__ out) {
    extern __shared__ unsigned char smem[];
    unsigned char* sAh = smem;
    unsigned char* sAl = smem + MT * ASTRIDE;
    unsigned char* sB  = smem + SM_B_OFF;

    const int tid  = threadIdx.x;
    const int lane = tid & 31;
    const int wid  = tid >> 5;
    const int m0   = blockIdx.x * MT;

    // -------------------- Phase A: aggregation into A tile --------------------
    const float inv = 1.0f / (float)SSAMP;
    #pragma unroll 1
    for (int rr = 0; rr < MT / 8; rr++) {
        int r = rr * 8 + wid;              // local row, warp-uniform
        int m = m0 + r;
        if (m >= NNODES) continue;

        unsigned char* hrow = sAh + r * ASTRIDE;
        unsigned char* lrow = sAl + r * ASTRIDE;

        // self feature (128 floats)
        float4 sf = *(const float4*)(node_feat + (size_t)m * NODE_DIM + lane * 4);

        // neighbor gather mean
        int s = 0;
        if (lane < SSAMP) s = src_idx[(size_t)m * SSAMP + lane];
        float4 na = make_float4(0.f, 0.f, 0.f, 0.f);
        #pragma unroll
        for (int q = 0; q < SSAMP; q++) {
            int sr = __shfl_sync(0xffffffffu, s, q);
            float4 v = *(const float4*)(node_feat + (size_t)sr * NODE_DIM + lane * 4);
            na.x += v.x; na.y += v.y; na.z += v.z; na.w += v.w;
        }
        na.x *= inv; na.y *= inv; na.z *= inv; na.w *= inv;

        // edge mean (64 cols): lanes split even/odd rows
        const float* ep = edge_feat + (size_t)m * (SSAMP * EDGE_DIM);
        int halfrow = lane >> 4, cg = lane & 15;
        float4 ea = make_float4(0.f, 0.f, 0.f, 0.f);
        #pragma unroll
        for (int q = 0; q < SSAMP; q += 2) {
            float4 v = *(const float4*)(ep + (size_t)(q + halfrow) * EDGE_DIM + cg * 4);
            ea.x += v.x; ea.y += v.y; ea.z += v.z; ea.w += v.w;
        }
        ea.x += __shfl_xor_sync(0xffffffffu, ea.x, 16);
        ea.y += __shfl_xor_sync(0xffffffffu, ea.y, 16);
        ea.z += __shfl_xor_sync(0xffffffffu, ea.z, 16);
        ea.w += __shfl_xor_sync(0xffffffffu, ea.w, 16);

        split_store(hrow, lrow, lane * 8, sf);               // k 0..127
        split_store(hrow, lrow, 256 + lane * 8, na);         // k 128..255
        if (lane < 16) {
            ea.x *= inv; ea.y *= inv; ea.z *= inv; ea.w *= inv;
            split_store(hrow, lrow, 512 + cg * 8, ea);       // k 256..319
        }
    }

    // -------------------- Phase B: GEMM over K=320 (20 k-steps) ---------------
    const uint32_t sAh32 = smem_u32(sAh);
    const uint32_t sAl32 = smem_u32(sAl);
    const uint32_t sB32  = smem_u32(sB);

    const int mw = (wid & 1) * 32;
    const int nw = (wid >> 1) * 32;
    const uint32_t aoff = (uint32_t)((mw + (lane & 15)) * ASTRIDE + (lane >> 4) * 16);
    const uint32_t boff = (uint32_t)((nw + ((lane >> 4) << 3) + (lane & 7)) * BSTRIDE
                                     + ((lane >> 3) & 1) * 16);

    // B slice loader: k-step s -> buffer b (hi + lo, 16 halfs per n-row)
    const int bn = tid >> 1, bu = tid & 1;
    const uint32_t bdst = sB32 + bn * BSTRIDE + bu * 16;
    const size_t   bsrc = (size_t)bn * (KTOT * 2) + (size_t)bu * 16;

    float C[2][4][4];
    #pragma unroll
    for (int a = 0; a < 2; a++)
        #pragma unroll
        for (int j = 0; j < 4; j++)
            #pragma unroll
            for (int q = 0; q < 4; q++) C[a][j][q] = 0.f;

    // prologue: stage k-step 0 into buffer 0
    cpa16(bdst, (const char*)g_Wh + bsrc);
    cpa16(bdst + BHALF, (const char*)g_Wl + bsrc);
    CP_COMMIT();

    #pragma unroll 1
    for (int s = 0; s < 20; s++) {
        CP_WAIT0();
        __syncthreads();                    // buf[s&1] ready; phase A / prev compute done
        if (s < 19) {                       // prefetch next k-step into other buffer
            uint32_t d = bdst + ((s + 1) & 1) * BBUF;
            size_t   g = bsrc + (size_t)(s + 1) * 32;
            cpa16(d, (const char*)g_Wh + g);
            cpa16(d + BHALF, (const char*)g_Wl + g);
            CP_COMMIT();
        }

        const uint32_t ab = aoff + (uint32_t)(s * 32);
        const uint32_t bb_base = sB32 + (uint32_t)((s & 1) * BBUF) + boff;

        uint32_t ah[2][4], al[2][4], bb[8];
        ldsm_x4(ah[0], sAh32 + ab);
        ldsm_x4(ah[1], sAh32 + ab + 16 * ASTRIDE);
        ldsm_x4(&bb[0], bb_base);
        ldsm_x4(&bb[4], bb_base + 16 * BSTRIDE);
        #pragma unroll
        for (int a = 0; a < 2; a++)
            #pragma unroll
            for (int j = 0; j < 4; j++)
                mma16816(C[a][j], ah[a], &bb[j * 2]);

        ldsm_x4(al[0], sAl32 + ab);
        ldsm_x4(al[1], sAl32 + ab + 16 * ASTRIDE);
        #pragma unroll
        for (int a = 0; a < 2; a++)
            #pragma unroll
            for (int j = 0; j < 4; j++)
                mma16816(C[a][j], al[a], &bb[j * 2]);

        ldsm_x4(&bb[0], bb_base + BHALF);
        ldsm_x4(&bb[4], bb_base + BHALF + 16 * BSTRIDE);
        #pragma unroll
        for (int a = 0; a < 2; a++)
            #pragma unroll
            for (int j = 0; j < 4; j++)
                mma16816(C[a][j], ah[a], &bb[j * 2]);
    }

    // -------------------- epilogue: bias + relu -> out -------------------------
    #pragma unroll
    for (int a = 0; a < 2; a++) {
        int row = m0 + mw + a * 16 + (lane >> 2);
        #pragma unroll
        for (int j = 0; j < 4; j++) {
            int col = nw + j * 8 + 2 * (lane & 3);
            float bx = g_bias[col], by = g_bias[col + 1];
            if (row < NNODES) {
                float2 o;
                o.x = fmaxf(C[a][j][0] + bx, 0.f);
                o.y = fmaxf(C[a][j][1] + by, 0.f);
                *(float2*)(out + (size_t)row * EMB_DIM + col) = o;
            }
            if (row + 8 < NNODES) {
                float2 o;
                o.x = fmaxf(C[a][j][2] + bx, 0.f);
                o.y = fmaxf(C[a][j][3] + by, 0.f);
                *(float2*)(out + (size_t)(row + 8) * EMB_DIM + col) = o;
            }
        }
    }
}

// ===========================================================================
// inputs: node_feat, edge_feat, src_idx, W_edge, b_edge, W_lin, b_lin
// ===========================================================================
extern "C" void kernel_launch(void* const* d_in, const int* in_sizes, int n_in,
                              void* d_out, int out_size) {
    const float* node_feat = (const float*)d_in[0];
    const float* edge_feat = (const float*)d_in[1];
    const int*   src_idx   = (const int*)  d_in[2];
    const float* W_edge    = (const float*)d_in[3];
    const float* b_edge    = (const float*)d_in[4];
    const float* W_lin     = (const float*)d_in[5];
    const float* b_lin     = (const float*)d_in[6];
    float*       out       = (float*)d_out;
    (void)in_sizes; (void)n_in; (void)out_size;

    static int smem_set = 0;
    if (!smem_set) {
        cudaFuncSetAttribute(sage_fused, cudaFuncAttributeMaxDynamicSharedMemorySize, SM_TOTAL);
        smem_set = 1;
    }

    fold_weights<<<41, 256>>>(W_edge, b_edge, W_lin, b_lin);

    int blocks = (NNODES + MT - 1) / MT;   // 1563
    sage_fused<<<blocks, 256, SM_TOTAL>>>(node_feat, edge_feat, src_idx, out);
}

// round 5
// speedup vs baseline: 1.5917x; 1.5917x over previous
#include <cuda_runtime.h>
#include <cuda_bf16.h>
#include <cstdint>

#define NNODES   100000
#define SSAMP    16
#define NODE_DIM 128
#define EDGE_DIM 64
#define EMB_DIM  128
#define KTOT     320            // 128 self + 128 neigh-agg + 64 edge-mean

// ---------------- device-global scratch (no allocs allowed) ------------------
// Materialized concat X = [self | neigh-mean | edge-mean], split bf16 hi/lo.
__device__ __align__(16) __nv_bfloat16 g_Xh[(size_t)NNODES * KTOT];
__device__ __align__(16) __nv_bfloat16 g_Xl[(size_t)NNODES * KTOT];
__device__ __align__(16) __nv_bfloat16 g_Wh[EMB_DIM * KTOT];  // folded W^T [n][k], hi
__device__ __align__(16) __nv_bfloat16 g_Wl[EMB_DIM * KTOT];  // lo
__device__ float g_bias[EMB_DIM];

// ---------------- helpers ----------------------------------------------------
__device__ __forceinline__ uint32_t smem_u32(const void* p) {
    uint32_t a;
    asm("{ .reg .u64 t; cvta.to.shared.u64 t, %1; cvt.u32.u64 %0, t; }" : "=r"(a) : "l"(p));
    return a;
}
__device__ __forceinline__ void ldsm_x4(uint32_t* r, uint32_t addr) {
    asm volatile("ldmatrix.sync.aligned.m8n8.x4.shared.b16 {%0,%1,%2,%3}, [%4];"
        : "=r"(r[0]), "=r"(r[1]), "=r"(r[2]), "=r"(r[3]) : "r"(addr));
}
__device__ __forceinline__ void mma16816(float* d, const uint32_t* a, const uint32_t* b) {
    asm volatile("mma.sync.aligned.m16n8k16.row.col.f32.bf16.bf16.f32 "
        "{%0,%1,%2,%3}, {%4,%5,%6,%7}, {%8,%9}, {%0,%1,%2,%3};"
        : "+f"(d[0]), "+f"(d[1]), "+f"(d[2]), "+f"(d[3])
        : "r"(a[0]), "r"(a[1]), "r"(a[2]), "r"(a[3]), "r"(b[0]), "r"(b[1]));
}
__device__ __forceinline__ void cpa16(uint32_t dst, const void* src) {
    asm volatile("cp.async.cg.shared.global [%0], [%1], 16;" :: "r"(dst), "l"(src));
}
#define CP_COMMIT() asm volatile("cp.async.commit_group;" ::: "memory")
#define CP_WAIT1()  asm volatile("cp.async.wait_group 1;" ::: "memory")
#define CP_WAIT0()  asm volatile("cp.async.wait_group 0;" ::: "memory")

// split fp32x4 -> bf16 hi/lo, store 8B each to GLOBAL
__device__ __forceinline__ void split_store_g(__nv_bfloat16* hp, __nv_bfloat16* lp, float4 v) {
    __nv_bfloat16 hx = __float2bfloat16_rn(v.x);
    __nv_bfloat16 hy = __float2bfloat16_rn(v.y);
    __nv_bfloat16 hz = __float2bfloat16_rn(v.z);
    __nv_bfloat16 hw = __float2bfloat16_rn(v.w);
    __nv_bfloat162 h01 = __halves2bfloat162(hx, hy);
    __nv_bfloat162 h23 = __halves2bfloat162(hz, hw);
    __nv_bfloat162 l01 = __floats2bfloat162_rn(v.x - __bfloat162float(hx),
                                               v.y - __bfloat162float(hy));
    __nv_bfloat162 l23 = __floats2bfloat162_rn(v.z - __bfloat162float(hz),
                                               v.w - __bfloat162float(hw));
    *(uint2*)hp = make_uint2(*(uint32_t*)&h01, *(uint32_t*)&h23);
    *(uint2*)lp = make_uint2(*(uint32_t*)&l01, *(uint32_t*)&l23);
}

// ===========================================================================
// K0: convert self features into g_X[:, 0:128] (blocks 0..3124)
//     + fold Wall = [W_lin ; W_edge@W_lin[128:]] -> g_Wh/g_Wl (blocks 3125..3165)
// ===========================================================================
#define CONVB 3125
#define FOLDB 41

__global__ __launch_bounds__(256) void convert_and_fold(
        const float* __restrict__ node_feat,
        const float* __restrict__ W_edge, const float* __restrict__ b_edge,
        const float* __restrict__ W_lin,  const float* __restrict__ b_lin) {
    if (blockIdx.x < CONVB) {
        int base = blockIdx.x * 4096;
        #pragma unroll
        for (int i = 0; i < 4; i++) {
            int idx = base + i * 1024 + threadIdx.x * 4;
            int row = idx >> 7, col = idx & 127;
            if (row < NNODES) {
                float4 v = *(const float4*)(node_feat + idx);
                split_store_g(g_Xh + (size_t)row * KTOT + col,
                              g_Xl + (size_t)row * KTOT + col, v);
            }
        }
        return;
    }
    int kid = blockIdx.x - CONVB;          // 0..40
    if (kid == 40) {
        int j = threadIdx.x;
        if (j < EMB_DIM) {
            float acc = b_lin[j];
            for (int c = 0; c < NODE_DIM; c++)
                acc += b_edge[c] * W_lin[(NODE_DIM + c) * EMB_DIM + j];
            g_bias[j] = acc;
        }
        return;
    }
    int kk = threadIdx.x >> 7;             // 0/1
    int j  = threadIdx.x & 127;            // output col n
    #pragma unroll
    for (int r = 0; r < 4; r++) {
        int k = kid * 8 + r * 2 + kk;      // 0..319
        float w;
        if (k < 2 * NODE_DIM) {
            w = W_lin[k * EMB_DIM + j];
        } else {
            int e = k - 2 * NODE_DIM;
            float acc = 0.f;
            #pragma unroll 4
            for (int c = 0; c < NODE_DIM; c++)
                acc += W_edge[e * NODE_DIM + c] * W_lin[(NODE_DIM + c) * EMB_DIM + j];
            w = acc;
        }
        __nv_bfloat16 h = __float2bfloat16_rn(w);
        g_Wh[j * KTOT + k] = h;
        g_Wl[j * KTOT + k] = __float2bfloat16_rn(w - __bfloat162float(h));
    }
}

// ===========================================================================
// K1: warp-per-node aggregation. Gather reads bf16-hi self rows (256B each).
//     Writes neigh-mean (k 128..255) and edge-mean (k 256..319) hi/lo.
// ===========================================================================
__global__ __launch_bounds__(256) void aggregate(
        const float* __restrict__ edge_feat,
        const int*   __restrict__ src_idx) {
    int node = (int)((blockIdx.x * blockDim.x + threadIdx.x) >> 5);
    if (node >= NNODES) return;
    int lane = threadIdx.x & 31;

    // ---- edge mean: lanes 0-15 even rows, 16-31 odd rows ----
    const float* ep = edge_feat + (size_t)node * (SSAMP * EDGE_DIM);
    int halfrow = lane >> 4, cg = lane & 15;
    float4 ea = make_float4(0.f, 0.f, 0.f, 0.f);
    #pragma unroll
    for (int r = 0; r < SSAMP; r += 2) {
        float4 v = *(const float4*)(ep + (size_t)(r + halfrow) * EDGE_DIM + cg * 4);
        ea.x += v.x; ea.y += v.y; ea.z += v.z; ea.w += v.w;
    }

    // ---- neighbor gather mean from bf16-hi rows ----
    int s = 0;
    if (lane < SSAMP) s = src_idx[(size_t)node * SSAMP + lane];
    float4 na = make_float4(0.f, 0.f, 0.f, 0.f);
    #pragma unroll
    for (int r = 0; r < SSAMP; r++) {
        int sr = __shfl_sync(0xffffffffu, s, r);
        uint2 pv = *(const uint2*)(g_Xh + (size_t)sr * KTOT + lane * 4);
        float2 f0 = __bfloat1622float2(*(const __nv_bfloat162*)&pv.x);
        float2 f1 = __bfloat1622float2(*(const __nv_bfloat162*)&pv.y);
        na.x += f0.x; na.y += f0.y; na.z += f1.x; na.w += f1.y;
    }

    ea.x += __shfl_xor_sync(0xffffffffu, ea.x, 16);
    ea.y += __shfl_xor_sync(0xffffffffu, ea.y, 16);
    ea.z += __shfl_xor_sync(0xffffffffu, ea.z, 16);
    ea.w += __shfl_xor_sync(0xffffffffu, ea.w, 16);

    const float inv = 1.0f / (float)SSAMP;
    na.x *= inv; na.y *= inv; na.z *= inv; na.w *= inv;
    split_store_g(g_Xh + (size_t)node * KTOT + 128 + lane * 4,
                  g_Xl + (size_t)node * KTOT + 128 + lane * 4, na);
    if (lane < 16) {
        ea.x *= inv; ea.y *= inv; ea.z *= inv; ea.w *= inv;
        split_store_g(g_Xh + (size_t)node * KTOT + 256 + cg * 4,
                      g_Xl + (size_t)node * KTOT + 256 + cg * 4, ea);
    }
}

// ===========================================================================
// K2: split-bf16 GEMM, cp.async double-buffered A+B staging.
//   out = relu( X @ W + bias );  X = g_Xh+g_Xl [N,320], W = g_Wh+g_Wl [320,128]
//   CTA 128x128, 8 warps (32x64 warp tile), 10 chunks of KC=32 (2 ksteps each).
// ===========================================================================
#define STRIDE   80                      // smem row stride bytes (64 data + 16 pad)
#define ABYTES   (128 * STRIDE)          // 10240 per array
#define STAGE    (4 * ABYTES)            // Ah, Al, Bh, Bl
#define SM_TOTAL (2 * STAGE)             // 81920

__global__ __launch_bounds__(256, 2) void gemm_mma(float* __restrict__ out) {
    extern __shared__ unsigned char smem[];
    const int tid  = threadIdx.x;
    const int lane = tid & 31;
    const int wid  = tid >> 5;
    const int m0   = blockIdx.x * 128;

    const int mw = (wid & 3) * 32;
    const int nw = (wid >> 2) * 64;
    const uint32_t sb = smem_u32(smem);
    const uint32_t aoff = (uint32_t)((mw + (lane & 15)) * STRIDE + (lane >> 4) * 16);
    const uint32_t boff = (uint32_t)((nw + ((lane >> 4) << 3) + (lane & 7)) * STRIDE
                                     + ((lane >> 3) & 1) * 16);

    // staging map: 2 (row,unit) pairs per thread per array
    int r0 = tid >> 2,         u0 = (tid & 3);
    int r1 = (tid + 256) >> 2, u1 = ((tid + 256) & 3);
    int am0 = m0 + r0; if (am0 >= NNODES) am0 = NNODES - 1;
    int am1 = m0 + r1; if (am1 >= NNODES) am1 = NNODES - 1;
    const char* aH0 = (const char*)g_Xh + (size_t)am0 * 640 + u0 * 16;
    const char* aH1 = (const char*)g_Xh + (size_t)am1 * 640 + u1 * 16;
    const char* aL0 = (const char*)g_Xl + (size_t)am0 * 640 + u0 * 16;
    const char* aL1 = (const char*)g_Xl + (size_t)am1 * 640 + u1 * 16;
    const char* bH0 = (const char*)g_Wh + (size_t)r0 * 640 + u0 * 16;
    const char* bH1 = (const char*)g_Wh + (size_t)r1 * 640 + u1 * 16;
    const char* bL0 = (const char*)g_Wl + (size_t)r0 * 640 + u0 * 16;
    const char* bL1 = (const char*)g_Wl + (size_t)r1 * 640 + u1 * 16;
    const uint32_t d0 = (uint32_t)(r0 * STRIDE + u0 * 16);
    const uint32_t d1 = (uint32_t)(r1 * STRIDE + u1 * 16);

    float C[2][8][4];
    #pragma unroll
    for (int a = 0; a < 2; a++)
        #pragma unroll
        for (int j = 0; j < 8; j++)
            #pragma unroll
            for (int q = 0; q < 4; q++) C[a][j][q] = 0.f;

    // prologue: stage chunk 0 into stage 0
    {
        uint32_t st = sb;
        cpa16(st + d0, aH0);            cpa16(st + d1, aH1);
        cpa16(st + ABYTES + d0, aL0);   cpa16(st + ABYTES + d1, aL1);
        cpa16(st + 2*ABYTES + d0, bH0); cpa16(st + 2*ABYTES + d1, bH1);
        cpa16(st + 3*ABYTES + d0, bL0); cpa16(st + 3*ABYTES + d1, bL1);
        CP_COMMIT();
    }

    #pragma unroll 1
    for (int ch = 0; ch < 10; ch++) {
        if (ch < 9) {
            uint32_t st = sb + ((ch + 1) & 1) * STAGE;
            size_t g = (size_t)(ch + 1) * 64;
            cpa16(st + d0, aH0 + g);            cpa16(st + d1, aH1 + g);
            cpa16(st + ABYTES + d0, aL0 + g);   cpa16(st + ABYTES + d1, aL1 + g);
            cpa16(st + 2*ABYTES + d0, bH0 + g); cpa16(st + 2*ABYTES + d1, bH1 + g);
            cpa16(st + 3*ABYTES + d0, bL0 + g); cpa16(st + 3*ABYTES + d1, bL1 + g);
            CP_COMMIT();
            CP_WAIT1();
        } else {
            CP_WAIT0();
        }
        __syncthreads();                        // chunk ch visible to all

        const uint32_t st  = sb + (ch & 1) * STAGE;
        const uint32_t sAh = st + aoff;
        const uint32_t sAl = st + ABYTES + aoff;
        const uint32_t sBh = st + 2 * ABYTES + boff;
        const uint32_t sBl = st + 3 * ABYTES + boff;

        #pragma unroll
        for (int s = 0; s < 2; s++) {
            const uint32_t kb = (uint32_t)(s * 32);
            uint32_t ah[2][4], al[2][4], bb[16];

            ldsm_x4(ah[0], sAh + kb);
            ldsm_x4(ah[1], sAh + 16 * STRIDE + kb);
            #pragma unroll
            for (int p = 0; p < 4; p++)
                ldsm_x4(&bb[4 * p], sBh + (uint32_t)(p * 16 * STRIDE) + kb);
            #pragma unroll
            for (int a = 0; a < 2; a++)
                #pragma unroll
                for (int j = 0; j < 8; j++)
                    mma16816(C[a][j], ah[a], &bb[j * 2]);

            ldsm_x4(al[0], sAl + kb);
            ldsm_x4(al[1], sAl + 16 * STRIDE + kb);
            #pragma unroll
            for (int a = 0; a < 2; a++)
                #pragma unroll
                for (int j = 0; j < 8; j++)
                    mma16816(C[a][j], al[a], &bb[j * 2]);

            #pragma unroll
            for (int p = 0; p < 4; p++)
                ldsm_x4(&bb[4 * p], sBl + (uint32_t)(p * 16 * STRIDE) + kb);
            #pragma unroll
            for (int a = 0; a < 2; a++)
                #pragma unroll
                for (int j = 0; j < 8; j++)
                    mma16816(C[a][j], ah[a], &bb[j * 2]);
        }
        __syncthreads();                        // all reads of stage ch done
    }

    // ---- epilogue: bias + relu -> out ----
    #pragma unroll
    for (int a = 0; a < 2; a++) {
        int row = m0 + mw + a * 16 + (lane >> 2);
        #pragma unroll
        for (int j = 0; j < 8; j++) {
            int col = nw + j * 8 + 2 * (lane & 3);
            float bx = g_bias[col], by = g_bias[col + 1];
            if (row < NNODES) {
                float2 o;
                o.x = fmaxf(C[a][j][0] + bx, 0.f);
                o.y = fmaxf(C[a][j][1] + by, 0.f);
                *(float2*)(out + (size_t)row * EMB_DIM + col) = o;
            }
            if (row + 8 < NNODES) {
                float2 o;
                o.x = fmaxf(C[a][j][2] + bx, 0.f);
                o.y = fmaxf(C[a][j][3] + by, 0.f);
                *(float2*)(out + (size_t)(row + 8) * EMB_DIM + col) = o;
            }
        }
    }
}

// ===========================================================================
// inputs: node_feat, edge_feat, src_idx, W_edge, b_edge, W_lin, b_lin
// ===========================================================================
extern "C" void kernel_launch(void* const* d_in, const int* in_sizes, int n_in,
                              void* d_out, int out_size) {
    const float* node_feat = (const float*)d_in[0];
    const float* edge_feat = (const float*)d_in[1];
    const int*   src_idx   = (const int*)  d_in[2];
    const float* W_edge    = (const float*)d_in[3];
    const float* b_edge    = (const float*)d_in[4];
    const float* W_lin     = (const float*)d_in[5];
    const float* b_lin     = (const float*)d_in[6];
    float*       out       = (float*)d_out;
    (void)in_sizes; (void)n_in; (void)out_size;

    static int smem_set = 0;
    if (!smem_set) {
        cudaFuncSetAttribute(gemm_mma, cudaFuncAttributeMaxDynamicSharedMemorySize, SM_TOTAL);
        smem_set = 1;
    }

    convert_and_fold<<<CONVB + FOLDB, 256>>>(node_feat, W_edge, b_edge, W_lin, b_lin);

    int agg_blocks = (NNODES * 32 + 255) / 256;   // 12500
    aggregate<<<agg_blocks, 256>>>(edge_feat, src_idx);

    int gemm_blocks = (NNODES + 127) / 128;       // 782
    gemm_mma<<<gemm_blocks, 256, SM_TOTAL>>>(out);
}